// round 3
// baseline (speedup 1.0000x reference)
#include <cuda_runtime.h>

#define NQ 22
#define NN (1 << NQ)
#define TB 14
#define TILE (1 << TB)
#define SMEM_F2 (TILE + (TILE >> 4))
#define SMEM_BYTES (SMEM_F2 * (int)sizeof(float2))
#define INV_SQRT_N 4.8828125e-4f  /* 1/2048 exact */

// single in-place state buffer (float4-typed for 16B-aligned vector loads)
__device__ float4 g_state4[NN / 2];

__device__ __forceinline__ float2* state_ptr() {
    return reinterpret_cast<float2*>(g_state4);
}

__device__ __forceinline__ int phys(int s) { return s + (s >> 4); }

// degree-7/6 polynomial sincos; |x| <~ 0.6 -> ~1e-6 abs error.
__device__ __forceinline__ void sincos_poly(float x, float& s, float& c) {
    float x2 = x * x;
    float p = fmaf(x2, -1.9841270e-4f, 8.3333338e-3f);
    p = fmaf(x2, p, -0.16666667f);
    s = x * fmaf(x2, p, 1.0f);
    float q = fmaf(x2, -1.3888889e-3f, 4.1666668e-2f);
    q = fmaf(x2, q, -0.5f);
    c = fmaf(x2, q, 1.0f);
}

// butterfly with cos(beta) factored out: a' = a + i*t*b ; b' = b + i*t*a
__device__ __forceinline__ void bf(float2& a, float2& b, float tb) {
    float ar = a.x, ai = a.y, br = b.x, bi = b.y;
    a.x = fmaf(-tb, bi, ar);
    a.y = fmaf( tb, br, ai);
    b.x = fmaf(-tb, ai, br);
    b.y = fmaf( tb, ar, bi);
}

// 4-bit butterfly over register index j (bits 0..3 of j)
__device__ __forceinline__ void bfly4(float2 r[16], float tb) {
#pragma unroll
    for (int j = 0; j < 16; j += 2) bf(r[j], r[j + 1], tb);
#pragma unroll
    for (int g = 0; g < 16; g += 4) {
        bf(r[g + 0], r[g + 2], tb);
        bf(r[g + 1], r[g + 3], tb);
    }
#pragma unroll
    for (int g = 0; g < 16; g += 8) {
#pragma unroll
        for (int u = 0; u < 4; u++) bf(r[g + u], r[g + u + 4], tb);
    }
#pragma unroll
    for (int u = 0; u < 8; u++) bf(r[u], r[u + 8], tb);
}

// Kernel A: butterflies on global-index bits 0..13 within a contiguous 2^14 tile.
// L==0: initialize state = (1/sqrt(N)) * exp(i*gamma[0]*h)   (no state read);
//       block 0 thread 0 also zeroes the output accumulator (consumed only by kB<1>).
// L==1: read state in place.
template <int L>
__global__ void __launch_bounds__(1024, 1)
kA(const float* __restrict__ h, const float* __restrict__ gam,
   const float* __restrict__ bet, float* __restrict__ out) {
    extern __shared__ float2 sm[];
    float2* st = state_ptr();
    const int t = threadIdx.x;
    const unsigned base = (unsigned)blockIdx.x << TB;
    const float tb = tanf(bet[L]);
    float2 r[16];

    if (L == 0 && blockIdx.x == 0 && t == 0) *out = 0.0f;

    // ---- stage 1: bits 0..3 (contiguous 16 elements per thread) ----
    if (L == 0) {
        const float g = gam[0];
        const float4* h4 = reinterpret_cast<const float4*>(h + base + t * 16);
#pragma unroll
        for (int q = 0; q < 4; q++) {
            float4 hv = h4[q];
            float xs[4] = {hv.x, hv.y, hv.z, hv.w};
#pragma unroll
            for (int u = 0; u < 4; u++) {
                float sn, cs;
                sincos_poly(g * xs[u], sn, cs);
                r[q * 4 + u] = make_float2(cs * INV_SQRT_N, sn * INV_SQRT_N);
            }
        }
    } else {
        const float4* c4 = &g_state4[(base >> 1) + t * 8];
#pragma unroll
        for (int q = 0; q < 8; q++) {
            float4 v = c4[q];
            r[2 * q + 0] = make_float2(v.x, v.y);
            r[2 * q + 1] = make_float2(v.z, v.w);
        }
    }
    bfly4(r, tb);
#pragma unroll
    for (int j = 0; j < 16; j++) sm[phys(t * 16 + j)] = r[j];
    __syncthreads();

    // ---- stage 2: bits 4..7 ----
    {
        const int lo = t & 15, hi = (t >> 4) << 8;
#pragma unroll
        for (int j = 0; j < 16; j++) r[j] = sm[phys(lo | (j << 4) | hi)];
        bfly4(r, tb);
#pragma unroll
        for (int j = 0; j < 16; j++) sm[phys(lo | (j << 4) | hi)] = r[j];
    }
    __syncthreads();

    // ---- stage 3: bits 8..11 ----
    {
        const int lo = t & 255, hi = (t >> 8) << 12;
#pragma unroll
        for (int j = 0; j < 16; j++) r[j] = sm[phys(lo | (j << 8) | hi)];
        bfly4(r, tb);
#pragma unroll
        for (int j = 0; j < 16; j++) sm[phys(lo | (j << 8) | hi)] = r[j];
    }
    __syncthreads();

    // ---- stage 4: bits 12..13 (j bits 0..1; j bits 2..3 passive = bits 10..11) ----
    {
#pragma unroll
        for (int j = 0; j < 16; j++)
            r[j] = sm[phys(t | ((j & 3) << 12) | ((j >> 2) << 10))];
#pragma unroll
        for (int g = 0; g < 16; g += 4) {
            bf(r[g + 0], r[g + 1], tb);
            bf(r[g + 2], r[g + 3], tb);
            bf(r[g + 0], r[g + 2], tb);
            bf(r[g + 1], r[g + 3], tb);
        }
#pragma unroll
        for (int j = 0; j < 16; j++)
            st[base + (unsigned)(t | ((j & 3) << 12) | ((j >> 2) << 10))] = r[j];
    }
}

// Kernel B: butterflies on global-index bits 14..21.
// Tile = 256 high-combos x 64 consecutive low elements; block index = bits 6..13.
// L==0: finish layer-1 mixing, then apply exp(i*gamma[1]*h), write state.
// L==1: finish layer-2 mixing, reduce sum(|c|^2 * hS) with cos^44 scale.
template <int L>
__global__ void __launch_bounds__(1024, 1)
kB(const float* __restrict__ h, const float* __restrict__ hS,
   const float* __restrict__ gam, const float* __restrict__ bet,
   float* __restrict__ out) {
    extern __shared__ float2 sm[];
    float2* st = state_ptr();
    const int t = threadIdx.x;
    const unsigned mid = blockIdx.x;  // bits 6..13
    const float tb = tanf(bet[L]);
    const int l6 = t & 63;
    const int th = t >> 6;  // 4 bits
    float2 r[16];

    // ---- stage B1: bits 14..17 (j), th = bits 18..21 ----
#pragma unroll
    for (int j = 0; j < 16; j++) {
        unsigned x = ((unsigned)((th << 4) | j) << TB) | (mid << 6) | (unsigned)l6;
        r[j] = st[x];
    }
    bfly4(r, tb);
#pragma unroll
    for (int j = 0; j < 16; j++) sm[phys((th << 10) | (j << 6) | l6)] = r[j];
    __syncthreads();

    // ---- stage B2: bits 18..21 (j), th = bits 14..17 ----
#pragma unroll
    for (int j = 0; j < 16; j++) r[j] = sm[phys((j << 10) | (th << 6) | l6)];
    bfly4(r, tb);

    if (L == 0) {
        const float g = gam[1];
#pragma unroll
        for (int j = 0; j < 16; j++) {
            unsigned x = ((unsigned)((j << 4) | th) << TB) | (mid << 6) | (unsigned)l6;
            float sn, cs;
            sincos_poly(g * h[x], sn, cs);
            float2 a = r[j];
            st[x] = make_float2(fmaf(a.x, cs, -a.y * sn), fmaf(a.x, sn, a.y * cs));
        }
    } else {
        float acc = 0.0f;
#pragma unroll
        for (int j = 0; j < 16; j++) {
            unsigned x = ((unsigned)((j << 4) | th) << TB) | (mid << 6) | (unsigned)l6;
            float2 a = r[j];
            acc = fmaf(fmaf(a.x, a.x, a.y * a.y), hS[x], acc);
        }
#pragma unroll
        for (int o = 16; o > 0; o >>= 1) acc += __shfl_xor_sync(0xffffffffu, acc, o);
        __syncthreads();  // done reading sm; reuse for block reduction
        float* red = reinterpret_cast<float*>(sm);
        if ((t & 31) == 0) red[t >> 5] = acc;
        __syncthreads();
        if (t < 32) {
            float v = red[t];
#pragma unroll
            for (int o = 16; o > 0; o >>= 1) v += __shfl_xor_sync(0xffffffffu, v, o);
            if (t == 0) {
                // fold out the factored cos(beta) per bit: amplitude scale
                // cb1^22 * cb2^22  ->  probability scale (cb1*cb2)^44
                float cb = cosf(bet[0]) * cosf(bet[1]);
                atomicAdd(out, v * powf(cb, 44.0f));
            }
        }
    }
}

extern "C" void kernel_launch(void* const* d_in, const int* in_sizes, int n_in,
                              void* d_out, int out_size) {
    const float* h   = (const float*)d_in[0];
    const float* hS  = (const float*)d_in[1];
    const float* gam = (const float*)d_in[2];
    const float* bet = (const float*)d_in[3];
    float* out = (float*)d_out;

    cudaFuncSetAttribute(kA<0>, cudaFuncAttributeMaxDynamicSharedMemorySize, SMEM_BYTES);
    cudaFuncSetAttribute(kA<1>, cudaFuncAttributeMaxDynamicSharedMemorySize, SMEM_BYTES);
    cudaFuncSetAttribute(kB<0>, cudaFuncAttributeMaxDynamicSharedMemorySize, SMEM_BYTES);
    cudaFuncSetAttribute(kB<1>, cudaFuncAttributeMaxDynamicSharedMemorySize, SMEM_BYTES);

    const int blocks = NN / TILE;  // 256

    // layer 1
    kA<0><<<blocks, 1024, SMEM_BYTES>>>(h, gam, bet, out);
    kB<0><<<blocks, 1024, SMEM_BYTES>>>(h, hS, gam, bet, out);
    // layer 2
    kA<1><<<blocks, 1024, SMEM_BYTES>>>(h, gam, bet, out);
    kB<1><<<blocks, 1024, SMEM_BYTES>>>(h, hS, gam, bet, out);
}